// round 3
// baseline (speedup 1.0000x reference)
#include <cuda_runtime.h>
#include <cstdint>

// SpatialCorrelationSampler: out[b, dy*9+dx, h, w] =
//   sum_c in1[b,c,h,w] * in2_zeropad4[b,c,h+dy,w+dx],  dy,dx in [0,9)
// Shapes: in1,in2 (B=4, C=256, H=128, W=128) fp32; out (B, 81, H, W) fp32.
//
// Round 3: 8-px strips + packed fma.rn.f32x2 + padded (conflict-free) smem
// rows + 3-stage cp.async ring with a single barrier per chunk.

namespace {

constexpr int C = 256, H = 128, W = 128;
constexpr int PATCH = 9, PAD = 4;

constexpr int TH = 8;            // tile rows
constexpr int TW = 32;           // tile cols
constexpr int CC = 8;            // channels per smem chunk
constexpr int S2H = TH + 8;      // 16 (halo rows)
constexpr int S2W = TW + 8;      // 40 (halo cols, real)
constexpr int S1P = 36;          // padded s1 row stride (floats)
constexpr int S2P = 44;          // padded s2 row stride (floats)
constexpr int NTHREADS = 4 * TH * PATCH;   // 288
constexpr int NCHUNK = C / CC;             // 32
constexpr int CHUNK_GBYTES = CC * H * W * 4;

constexpr int S1_REAL_V4 = CC * TH * (TW / 4);     // 512
constexpr int S2_REAL_V4 = CC * S2H * (S2W / 4);   // 1280
constexpr int TOT_V4 = S1_REAL_V4 + S2_REAL_V4;    // 1792
constexpr int SLOTS = (TOT_V4 + NTHREADS - 1) / NTHREADS;  // 7

constexpr int S1_FLOATS = CC * TH * S1P;            // 2304
constexpr int S2_FLOATS = CC * S2H * S2P;           // 5632
constexpr int STAGE_FLOATS = S1_FLOATS + S2_FLOATS; // 7936
constexpr int STAGES = 3;
constexpr int SMEM_BYTES = STAGES * STAGE_FLOATS * 4;   // 95232

__device__ __forceinline__ uint64_t fma2(uint64_t a, uint64_t b, uint64_t c) {
    uint64_t d;
    asm("fma.rn.f32x2 %0, %1, %2, %3;" : "=l"(d) : "l"(a), "l"(b), "l"(c));
    return d;
}
__device__ __forceinline__ uint64_t pk2(float lo, float hi) {
    uint64_t d;
    asm("mov.b64 %0, {%1, %2};" : "=l"(d) : "f"(lo), "f"(hi));
    return d;
}
__device__ __forceinline__ void upk2(uint64_t v, float& lo, float& hi) {
    asm("mov.b64 {%0, %1}, %2;" : "=f"(lo), "=f"(hi) : "l"(v));
}

__device__ __forceinline__ void cp16(uint32_t dst_smem, const void* src) {
    asm volatile("cp.async.cg.shared.global [%0], [%1], 16;"
                 :: "r"(dst_smem), "l"(src));
}
__device__ __forceinline__ void cp_commit() {
    asm volatile("cp.async.commit_group;" ::: "memory");
}
__device__ __forceinline__ void cp_wait1() {
    asm volatile("cp.async.wait_group 1;" ::: "memory");
}

__global__ __launch_bounds__(NTHREADS, 2)
void corr_kernel(const float* __restrict__ in1,
                 const float* __restrict__ in2,
                 float* __restrict__ out) {
    extern __shared__ float smem[];
    const uint32_t smem_u32 = (uint32_t)__cvta_generic_to_shared(smem);

    const int b  = blockIdx.z;
    const int h0 = blockIdx.y * TH;
    const int w0 = blockIdx.x * TW;
    const int tid = threadIdx.x;

    // ---------------- copy-slot precompute --------------------------------
    uint32_t soff[SLOTS];   // byte offset within a stage
    uint32_t goff[SLOTS];   // byte offset from tensor base (chunk 0); ~0 = skip
    bool     is1[SLOTS];
#pragma unroll
    for (int i = 0; i < SLOTS; ++i) {
        int f = tid + i * NTHREADS;
        goff[i] = 0xFFFFFFFFu;
        soff[i] = 0;
        is1[i]  = false;
        if (f < S1_REAL_V4) {
            int c = f >> 6, rem = f & 63;
            int row = rem >> 3, col4 = rem & 7;
            soff[i] = ((c * TH + row) * S1P + col4 * 4) * 4;
            goff[i] = (uint32_t)((((b * C + c) * H + (h0 + row)) * W
                                  + w0 + col4 * 4) * 4);
            is1[i] = true;
        } else if (f < TOT_V4) {
            int u = f - S1_REAL_V4;
            int c = u / 160, rem = u % 160;
            int row = rem / 10, col4 = rem % 10;
            soff[i] = (S1_FLOATS + (c * S2H + row) * S2P + col4 * 4) * 4;
            int gy = h0 + row - PAD;
            int gx = w0 + col4 * 4 - PAD;      // 16B aligned: all-in or all-out
            if (gy >= 0 && gy < H && gx >= 0 && gx < W) {
                goff[i] = (uint32_t)((((b * C + c) * H + gy) * W + gx) * 4);
            } else {
                float4 z = make_float4(0.f, 0.f, 0.f, 0.f);
#pragma unroll
                for (int s = 0; s < STAGES; ++s)
                    *(float4*)((char*)smem + s * STAGE_FLOATS * 4 + soff[i]) = z;
            }
        }
    }

    auto issue_chunk = [&](int ch) {
        uint32_t sbase = smem_u32 + (uint32_t)((ch % STAGES) * STAGE_FLOATS * 4);
        size_t gchunk = (size_t)ch * CHUNK_GBYTES;
#pragma unroll
        for (int i = 0; i < SLOTS; ++i) {
            if (goff[i] != 0xFFFFFFFFu) {
                const char* base = is1[i] ? (const char*)in1 : (const char*)in2;
                cp16(sbase + soff[i], base + gchunk + goff[i]);
            }
        }
        cp_commit();
    };

    // OOB zeroing above races with nothing (cp targets are disjoint), but the
    // zeros must be visible before any thread computes: the first cp_wait1 +
    // __syncthreads below covers it.
    issue_chunk(0);
    issue_chunk(1);

    // ---------------- compute-role mapping --------------------------------
    const int sx = tid & 3;          // 8-pixel strip (col = sx*8)
    const int hy = (tid >> 2) & 7;   // row within tile
    const int dy = tid >> 5;         // 0..8

    const int a_off = hy * S1P + sx * 8;
    const int r_off = (hy + dy) * S2P + sx * 8;

    uint64_t acc[9][4];
#pragma unroll
    for (int i = 0; i < 9; ++i)
#pragma unroll
        for (int q = 0; q < 4; ++q) acc[i][q] = 0ull;

    for (int ch = 0; ch < NCHUNK; ++ch) {
        cp_wait1();                 // group ch complete (groups ch, ch+1 pending)
        __syncthreads();            // all threads see stage ch; all finished
                                    // reading stage (ch+2)%3 (during iter ch-1)

        if (ch + 2 < NCHUNK) issue_chunk(ch + 2);
        else cp_commit();           // keep group accounting uniform

        const float* st  = smem + (ch % STAGES) * STAGE_FLOATS;
        const float* s1f = st;
        const float* s2f = st + S1_FLOATS;

#pragma unroll
        for (int c = 0; c < CC; ++c) {
            const float* p1 = s1f + c * (TH * S1P) + a_off;
            const float* p2 = s2f + c * (S2H * S2P) + r_off;
            float4 A0 = *(const float4*)(p1);
            float4 A1 = *(const float4*)(p1 + 4);
            float4 R0 = *(const float4*)(p2);
            float4 R1 = *(const float4*)(p2 + 4);
            float4 R2 = *(const float4*)(p2 + 8);
            float4 R3 = *(const float4*)(p2 + 12);

            float r[16] = {R0.x, R0.y, R0.z, R0.w, R1.x, R1.y, R1.z, R1.w,
                           R2.x, R2.y, R2.z, R2.w, R3.x, R3.y, R3.z, R3.w};

            uint64_t a2[4] = {pk2(A0.x, A0.y), pk2(A0.z, A0.w),
                              pk2(A1.x, A1.y), pk2(A1.z, A1.w)};
            uint64_t e[8], o[7];
#pragma unroll
            for (int j = 0; j < 8; ++j) e[j] = pk2(r[2 * j], r[2 * j + 1]);
#pragma unroll
            for (int j = 0; j < 7; ++j) o[j] = pk2(r[2 * j + 1], r[2 * j + 2]);

#pragma unroll
            for (int dx = 0; dx < 9; ++dx) {
#pragma unroll
                for (int q = 0; q < 4; ++q) {
                    int k = dx + 2 * q;
                    uint64_t rp = (dx & 1) ? o[(k - 1) >> 1] : e[k >> 1];
                    acc[dx][q] = fma2(a2[q], rp, acc[dx][q]);
                }
            }
        }
    }

    // ---------------- epilogue --------------------------------------------
    const int h = h0 + hy;
    const int wb = w0 + sx * 8;
#pragma unroll
    for (int dx = 0; dx < 9; ++dx) {
        float v[8];
#pragma unroll
        for (int q = 0; q < 4; ++q) upk2(acc[dx][q], v[2 * q], v[2 * q + 1]);
        int p = dy * 9 + dx;
        float* op = out + (((size_t)b * (PATCH * PATCH) + p) * H + h) * W + wb;
        *(float4*)(op)     = make_float4(v[0], v[1], v[2], v[3]);
        *(float4*)(op + 4) = make_float4(v[4], v[5], v[6], v[7]);
    }
}

}  // namespace

extern "C" void kernel_launch(void* const* d_in, const int* in_sizes, int n_in,
                              void* d_out, int out_size) {
    const float* in1 = (const float*)d_in[0];
    const float* in2 = (const float*)d_in[1];
    float* out = (float*)d_out;

    cudaFuncSetAttribute(corr_kernel,
                         cudaFuncAttributeMaxDynamicSharedMemorySize,
                         SMEM_BYTES);

    int B = in_sizes[0] / (C * H * W);   // = 4
    dim3 grid(W / TW, H / TH, B);        // (4, 16, 4) = 256 blocks
    corr_kernel<<<grid, NTHREADS, SMEM_BYTES>>>(in1, in2, out);
}

// round 4
// speedup vs baseline: 1.2782x; 1.2782x over previous
#include <cuda_runtime.h>
#include <cstdint>

// SpatialCorrelationSampler: out[b, dy*9+dx, h, w] =
//   sum_c in1[b,c,h,w] * in2_zeropad4[b,c,h+dy,w+dx],  dy,dx in [0,9)
// Shapes: in1,in2 (B=4, C=256, H=128, W=128) fp32; out (B, 81, H, W) fp32.
//
// Round 4: P=8 pixel strips, pure scalar FFMA (no f32x2 packing), padded
// conflict-free smem, 3-stage cp.async ring, one barrier per chunk,
// 2 blocks/SM co-residency (whole 256-block grid resident in one wave).

namespace {

constexpr int C = 256, H = 128, W = 128;
constexpr int PATCH = 9, PAD = 4;

constexpr int TH = 8;            // tile rows
constexpr int TW = 32;           // tile cols
constexpr int CC = 8;            // channels per smem chunk
constexpr int S2H = TH + 8;      // 16 (halo rows)
constexpr int S2W = TW + 8;      // 40 (halo cols, real)
constexpr int S1P = 36;          // padded s1 row stride (floats)
constexpr int S2P = 44;          // padded s2 row stride (floats)
constexpr int NTHREADS = 4 * TH * PATCH;   // 288
constexpr int NCHUNK = C / CC;             // 32
constexpr int CHUNK_GBYTES = CC * H * W * 4;

constexpr int S1_REAL_V4 = CC * TH * (TW / 4);     // 512
constexpr int S2_REAL_V4 = CC * S2H * (S2W / 4);   // 1280
constexpr int TOT_V4 = S1_REAL_V4 + S2_REAL_V4;    // 1792
constexpr int SLOTS = (TOT_V4 + NTHREADS - 1) / NTHREADS;  // 7

constexpr int S1_FLOATS = CC * TH * S1P;            // 2304
constexpr int S2_FLOATS = CC * S2H * S2P;           // 5632
constexpr int STAGE_FLOATS = S1_FLOATS + S2_FLOATS; // 7936
constexpr int STAGES = 3;
constexpr int SMEM_BYTES = STAGES * STAGE_FLOATS * 4;   // 95232 (x2 blocks fits)

__device__ __forceinline__ void cp16(uint32_t dst_smem, const void* src) {
    asm volatile("cp.async.cg.shared.global [%0], [%1], 16;"
                 :: "r"(dst_smem), "l"(src));
}
__device__ __forceinline__ void cp_commit() {
    asm volatile("cp.async.commit_group;" ::: "memory");
}
__device__ __forceinline__ void cp_wait1() {
    asm volatile("cp.async.wait_group 1;" ::: "memory");
}

__global__ __launch_bounds__(NTHREADS, 2)
void corr_kernel(const float* __restrict__ in1,
                 const float* __restrict__ in2,
                 float* __restrict__ out) {
    extern __shared__ float smem[];
    const uint32_t smem_u32 = (uint32_t)__cvta_generic_to_shared(smem);

    const int b  = blockIdx.z;
    const int h0 = blockIdx.y * TH;
    const int w0 = blockIdx.x * TW;
    const int tid = threadIdx.x;

    // ---------------- copy-slot precompute --------------------------------
    uint32_t soff[SLOTS];   // byte offset within a stage
    uint32_t goff[SLOTS];   // byte offset from tensor base (chunk 0); ~0 = skip
    bool     is1[SLOTS];
#pragma unroll
    for (int i = 0; i < SLOTS; ++i) {
        int f = tid + i * NTHREADS;
        goff[i] = 0xFFFFFFFFu;
        soff[i] = 0;
        is1[i]  = false;
        if (f < S1_REAL_V4) {
            int c = f >> 6, rem = f & 63;
            int row = rem >> 3, col4 = rem & 7;
            soff[i] = ((c * TH + row) * S1P + col4 * 4) * 4;
            goff[i] = (uint32_t)((((b * C + c) * H + (h0 + row)) * W
                                  + w0 + col4 * 4) * 4);
            is1[i] = true;
        } else if (f < TOT_V4) {
            int u = f - S1_REAL_V4;
            int c = u / 160, rem = u % 160;
            int row = rem / 10, col4 = rem % 10;
            soff[i] = (S1_FLOATS + (c * S2H + row) * S2P + col4 * 4) * 4;
            int gy = h0 + row - PAD;
            int gx = w0 + col4 * 4 - PAD;      // 16B aligned: all-in or all-out
            if (gy >= 0 && gy < H && gx >= 0 && gx < W) {
                goff[i] = (uint32_t)((((b * C + c) * H + gy) * W + gx) * 4);
            } else {
                // zero OOB halo slot once per stage; cp never touches it
                float4 z = make_float4(0.f, 0.f, 0.f, 0.f);
#pragma unroll
                for (int s = 0; s < STAGES; ++s)
                    *(float4*)((char*)smem + s * STAGE_FLOATS * 4 + soff[i]) = z;
            }
        }
    }

    auto issue_chunk = [&](int ch) {
        uint32_t sbase = smem_u32 + (uint32_t)((ch % STAGES) * STAGE_FLOATS * 4);
        size_t gchunk = (size_t)ch * CHUNK_GBYTES;
#pragma unroll
        for (int i = 0; i < SLOTS; ++i) {
            if (goff[i] != 0xFFFFFFFFu) {
                const char* base = is1[i] ? (const char*)in1 : (const char*)in2;
                cp16(sbase + soff[i], base + gchunk + goff[i]);
            }
        }
        cp_commit();
    };

    issue_chunk(0);
    issue_chunk(1);

    // ---------------- compute-role mapping --------------------------------
    const int sx = tid & 3;          // 8-pixel strip (col = sx*8)
    const int hy = (tid >> 2) & 7;   // row within tile
    const int dy = tid >> 5;         // 0..8

    const int a_off = hy * S1P + sx * 8;
    const int r_off = (hy + dy) * S2P + sx * 8;

    float acc[9][8];
#pragma unroll
    for (int i = 0; i < 9; ++i)
#pragma unroll
        for (int j = 0; j < 8; ++j) acc[i][j] = 0.f;

    for (int ch = 0; ch < NCHUNK; ++ch) {
        cp_wait1();                 // group ch landed (groups ch, ch+1 pending)
        __syncthreads();            // stage ch visible; everyone done reading
                                    // stage (ch+2)%3 during iteration ch-1

        if (ch + 2 < NCHUNK) issue_chunk(ch + 2);
        else cp_commit();           // keep group accounting uniform

        const float* st  = smem + (ch % STAGES) * STAGE_FLOATS;
        const float* s1f = st;
        const float* s2f = st + S1_FLOATS;

#pragma unroll
        for (int c = 0; c < CC; ++c) {
            const float* p1 = s1f + c * (TH * S1P) + a_off;
            const float* p2 = s2f + c * (S2H * S2P) + r_off;
            float4 A0 = *(const float4*)(p1);
            float4 A1 = *(const float4*)(p1 + 4);
            float4 R0 = *(const float4*)(p2);
            float4 R1 = *(const float4*)(p2 + 4);
            float4 R2 = *(const float4*)(p2 + 8);
            float4 R3 = *(const float4*)(p2 + 12);

            float a[8] = {A0.x, A0.y, A0.z, A0.w, A1.x, A1.y, A1.z, A1.w};
            float r[16] = {R0.x, R0.y, R0.z, R0.w, R1.x, R1.y, R1.z, R1.w,
                           R2.x, R2.y, R2.z, R2.w, R3.x, R3.y, R3.z, R3.w};

#pragma unroll
            for (int dx = 0; dx < 9; ++dx)
#pragma unroll
                for (int px = 0; px < 8; ++px)
                    acc[dx][px] = fmaf(a[px], r[px + dx], acc[dx][px]);
        }
    }

    // ---------------- epilogue --------------------------------------------
    const int h = h0 + hy;
    const int wb = w0 + sx * 8;
#pragma unroll
    for (int dx = 0; dx < 9; ++dx) {
        int p = dy * 9 + dx;
        float* op = out + (((size_t)b * (PATCH * PATCH) + p) * H + h) * W + wb;
        *(float4*)(op)     = make_float4(acc[dx][0], acc[dx][1],
                                         acc[dx][2], acc[dx][3]);
        *(float4*)(op + 4) = make_float4(acc[dx][4], acc[dx][5],
                                         acc[dx][6], acc[dx][7]);
    }
}

}  // namespace

extern "C" void kernel_launch(void* const* d_in, const int* in_sizes, int n_in,
                              void* d_out, int out_size) {
    const float* in1 = (const float*)d_in[0];
    const float* in2 = (const float*)d_in[1];
    float* out = (float*)d_out;

    cudaFuncSetAttribute(corr_kernel,
                         cudaFuncAttributeMaxDynamicSharedMemorySize,
                         SMEM_BYTES);

    int B = in_sizes[0] / (C * H * W);   // = 4
    dim3 grid(W / TW, H / TH, B);        // (4, 16, 4) = 256 blocks
    corr_kernel<<<grid, NTHREADS, SMEM_BYTES>>>(in1, in2, out);
}